// round 1
// baseline (speedup 1.0000x reference)
#include <cuda_runtime.h>
#include <cstdint>

#define HH 256
#define WW 256
#define NUM_CURVES 256
#define NUM_SAMPLES 32
#define NUM_BEZIERS 2
#define GPER (NUM_BEZIERS*NUM_SAMPLES)     /* 64 */
#define NGAUSS (NUM_CURVES*GPER)           /* 16384 */
#define LOG2E 1.4426950408889634f
#define BATCH 1024
#define SUB 4

// ---- static scratch (no allocations allowed) ----
__device__ int    d_order[NUM_CURVES];
__device__ float4 d_curveConic[NUM_CURVES];  // c0p, c1p, c2p, log2(alpha)
__device__ float4 d_curveColEx[NUM_CURVES];  // cr, cg, cb, ex
__device__ float  d_curveEy[NUM_CURVES];

__device__ float4 d_gA[NGAUSS];     // mx, my, c0p, c1p
__device__ float4 d_gB[NGAUSS];     // c2p, l2a, cr, cg
__device__ float  d_gCb[NGAUSS];    // cb
__device__ float4 d_gCull[NGAUSS];  // mx, my, ex, ey

// ---------------------------------------------------------------------------
// K1: per-curve preprocessing + stable depth ranking (1 block, 256 threads)
// ---------------------------------------------------------------------------
__global__ void k_prep(const float* __restrict__ chol,
                       const float* __restrict__ fdc,
                       const float* __restrict__ opac,
                       const float* __restrict__ depth)
{
    __shared__ float sd[NUM_CURVES];
    int i = threadIdx.x;
    float d = depth[i];
    sd[i] = d;
    __syncthreads();

    // stable rank (matches jnp.argsort stable on repeated depths)
    int rank = 0;
    #pragma unroll 8
    for (int j = 0; j < NUM_CURVES; ++j) {
        float dj = sd[j];
        rank += (dj < d) || (dj == d && j < i);
    }

    float c0 = chol[3*i+0] + 0.5f;
    float c1 = chol[3*i+1];
    float c2 = chol[3*i+2] + 0.5f;
    float s00 = c0*c0;
    float s01 = c0*c1;
    float s11 = c1*c1 + c2*c2;
    float det = s00*s11 - s01*s01;
    float inv = 1.0f / det;
    float A =  s11*inv;   // conic0
    float B = -s01*inv;   // conic1
    float C =  s00*inv;   // conic2

    float al  = 1.0f / (1.0f + expf(-opac[i]));
    float l2a = log2f(al);

    // cull radius: a = al*exp(-q/2) >= ~3.4e-9  =>  q <= 2*(19.5 + ln al)
    float Q = 2.0f * (19.5f + logf(al));
    Q = fmaxf(Q, 0.0f);
    float ex = sqrtf(Q * s00);
    float ey = sqrtf(Q * s11);

    float cr = 1.0f / (1.0f + expf(-fdc[3*i+0]));
    float cg = 1.0f / (1.0f + expf(-fdc[3*i+1]));
    float cb = 1.0f / (1.0f + expf(-fdc[3*i+2]));

    d_order[rank]      = i;
    d_curveConic[rank] = make_float4(-0.5f*LOG2E*A, -LOG2E*B, -0.5f*LOG2E*C, l2a);
    d_curveColEx[rank] = make_float4(cr, cg, cb, ex);
    d_curveEy[rank]    = ey;
}

// ---------------------------------------------------------------------------
// K2: Bezier evaluation -> per-gaussian packed data in depth-sorted order
// ---------------------------------------------------------------------------
__global__ void k_means(const float* __restrict__ ctrl)
{
    int g = blockIdx.x * 256 + threadIdx.x;        // 0..16383
    int cs    = g >> 6;                            // sorted curve slot
    int curve = d_order[cs];
    int k = (g >> 5) & 1;                          // bezier segment
    int s = g & 31;                                // sample

    float t = 0.007f + (float)s * (0.986f / 31.0f);
    float u = 1.0f - t;
    float t2 = t*t, t3 = t2*t, t4 = t2*t2, t5 = t4*t;
    float u2 = u*u, u3 = u2*u, u4 = u2*u2, u5 = u4*u;
    float w[6];
    w[0] = u5;
    w[1] = 5.0f  * t  * u4;
    w[2] = 10.0f * t2 * u3;
    w[3] = 10.0f * t3 * u2;
    w[4] = 5.0f  * t4 * u;
    w[5] = t5;

    const float* cbase = ctrl + curve * 10 * 2;
    float px = 0.0f, py = 0.0f;
    #pragma unroll
    for (int j = 0; j < 6; ++j) {
        int idx = k*5 + j;          // seg0: 0..5  seg1: 5..9,0 (wrap)
        if (idx >= 10) idx -= 10;
        px = fmaf(w[j], cbase[idx*2+0], px);
        py = fmaf(w[j], cbase[idx*2+1], py);
    }
    float mx = (tanhf(px)*0.5f + 0.5f) * (float)WW;
    float my = (tanhf(py)*0.5f + 0.5f) * (float)HH;

    float4 cc = d_curveConic[cs];
    float4 ce = d_curveColEx[cs];
    d_gA[g]    = make_float4(mx, my, cc.x, cc.y);
    d_gB[g]    = make_float4(cc.z, cc.w, ce.x, ce.y);
    d_gCb[g]   = ce.z;
    d_gCull[g] = make_float4(mx, my, ce.w, d_curveEy[cs]);
}

// ---------------------------------------------------------------------------
// K3: tiled alpha compositing. 256 blocks (16x16 tiles), 256 threads (pixel).
// ---------------------------------------------------------------------------
__global__ void __launch_bounds__(256)
k_render(const float* __restrict__ bgp, float* __restrict__ out)
{
    __shared__ float4 shA[BATCH];
    __shared__ float4 shB[BATCH];
    __shared__ float  shCb[BATCH];
    __shared__ int    warpTot[SUB][8];

    int t    = threadIdx.x;
    int wid  = t >> 5;
    int lane = t & 31;
    int tileX = blockIdx.x & 15;
    int tileY = blockIdx.x >> 4;
    float tcx = tileX*16 + 8.0f;
    float tcy = tileY*16 + 8.0f;
    int pc = t & 15, pr = t >> 4;
    float px = (float)(tileX*16 + pc) + 0.5f;
    float py = (float)(tileY*16 + pr) + 0.5f;

    float T = 1.0f, cr = 0.0f, cg = 0.0f, cb = 0.0f;

    for (int base = 0; base < NGAUSS; base += BATCH) {
        if (__syncthreads_and(T < 1e-4f)) break;   // all pixels saturated

        // --- cull SUB*256 gaussians, order-preserving ---
        unsigned bal[SUB];
        int flag[SUB];
        #pragma unroll
        for (int j = 0; j < SUB; ++j) {
            int gidx = base + j*256 + t;
            float4 cu = d_gCull[gidx];
            bool hit = (fabsf(cu.x - tcx) <= cu.z + 8.0f) &&
                       (fabsf(cu.y - tcy) <= cu.w + 8.0f);
            flag[j] = hit;
            unsigned bb = __ballot_sync(0xffffffffu, hit);
            bal[j] = bb;
            if (lane == 0) warpTot[j][wid] = __popc(bb);
        }
        __syncthreads();

        int subBase[SUB];
        int running = 0;
        #pragma unroll
        for (int j = 0; j < SUB; ++j) {
            subBase[j] = running;
            #pragma unroll
            for (int w = 0; w < 8; ++w) running += warpTot[j][w];
        }
        int total = running;

        #pragma unroll
        for (int j = 0; j < SUB; ++j) {
            if (flag[j]) {
                int off = subBase[j] + __popc(bal[j] & ((1u << lane) - 1u));
                #pragma unroll
                for (int w = 0; w < 8; ++w)
                    if (w < wid) off += warpTot[j][w];
                int gidx = base + j*256 + t;
                shA[off]  = d_gA[gidx];
                shB[off]  = d_gB[gidx];
                shCb[off] = d_gCb[gidx];
            }
        }
        __syncthreads();

        // --- composite survivors front-to-back ---
        if (T >= 1e-4f) {
            for (int i = 0; i < total; ++i) {
                float4 A = shA[i];
                float4 B = shB[i];
                float dx = px - A.x;
                float dy = py - A.y;
                float e = B.y;                       // log2(alpha)
                e = fmaf(A.z, dx*dx, e);             // c0'
                e = fmaf(A.w, dx*dy, e);             // c1'
                e = fmaf(B.x, dy*dy, e);             // c2'
                float a;
                asm("ex2.approx.f32 %0, %1;" : "=f"(a) : "f"(e));
                a = fminf(a, 0.999f);
                float w = a * T;
                cr = fmaf(w, B.z, cr);
                cg = fmaf(w, B.w, cg);
                cb = fmaf(w, shCb[i], cb);
                T -= w;                              // T *= (1-a)
            }
        }
    }

    float b0 = bgp[0], b1 = bgp[1], b2 = bgp[2];
    cr = fminf(fmaxf(fmaf(T, b0, cr), 0.0f), 1.0f);
    cg = fminf(fmaxf(fmaf(T, b1, cg), 0.0f), 1.0f);
    cb = fminf(fmaxf(fmaf(T, b2, cb), 0.0f), 1.0f);

    int row = tileY*16 + pr;
    int col = tileX*16 + pc;
    int o = (row*WW + col) * 3;
    out[o+0] = cr;
    out[o+1] = cg;
    out[o+2] = cb;
}

// ---------------------------------------------------------------------------
extern "C" void kernel_launch(void* const* d_in, const int* in_sizes, int n_in,
                              void* d_out, int out_size)
{
    const float* ctrl  = (const float*)d_in[0];  // (256,10,2)
    const float* fdc   = (const float*)d_in[1];  // (256,3)
    const float* chol  = (const float*)d_in[2];  // (256,3)
    const float* opac  = (const float*)d_in[3];  // (256,1)
    const float* depth = (const float*)d_in[4];  // (256,1)
    const float* bg    = (const float*)d_in[5];  // (3,)
    float* out = (float*)d_out;                  // (256,256,3)

    k_prep<<<1, 256>>>(chol, fdc, opac, depth);
    k_means<<<NGAUSS/256, 256>>>(ctrl);
    k_render<<<256, 256>>>(bg, out);
}